// round 7
// baseline (speedup 1.0000x reference)
#include <cuda_runtime.h>
#include <cstdint>

// Stain normalization: out = sat(exp( log(x+1e-6) @ C - beta )),  C[c][d] = M[c][d]*gamma[d]
//
// At the HBM floor (403 MB @ ~6.34 TB/s sustained). This variant keeps the
// proven smem-staged structure and upgrades global ld/st to 256-bit
// (ld/st.global.cs.v8.f32, sm_100+): one warp instruction moves 1 KB = 8 full
// 128B lines, halving global-path instruction/wavefront-issue count.

constexpr int TPB = 256;
constexpr int TILE_FLOATS = 6144;                 // 24 KB = 512 pixel-groups (4 px each)
constexpr int V8_PER_THREAD = 3;                  // 3 x 8 floats = 24 floats/thread
constexpr int GROUPS_PER_TILE = TILE_FLOATS / 12; // 512

__device__ __forceinline__ void ldg256_cs(const float* g, float r[8]) {
    asm volatile("ld.global.cs.v8.f32 {%0,%1,%2,%3,%4,%5,%6,%7}, [%8];"
                 : "=f"(r[0]), "=f"(r[1]), "=f"(r[2]), "=f"(r[3]),
                   "=f"(r[4]), "=f"(r[5]), "=f"(r[6]), "=f"(r[7])
                 : "l"(g));
}

__device__ __forceinline__ void stg256_cs(float* g, const float r[8]) {
    asm volatile("st.global.cs.v8.f32 [%0], {%1,%2,%3,%4,%5,%6,%7,%8};"
                 :: "l"(g),
                    "f"(r[0]), "f"(r[1]), "f"(r[2]), "f"(r[3]),
                    "f"(r[4]), "f"(r[5]), "f"(r[6]), "f"(r[7])
                 : "memory");
}

__global__ __launch_bounds__(TPB)
void stain_norm_v8_kernel(const float* __restrict__ x,
                          const float* __restrict__ M,
                          const float* __restrict__ gamma,
                          const float* __restrict__ beta,
                          float* __restrict__ out)
{
    __shared__ alignas(128) float s[TILE_FLOATS];

    const float* gsrc = x   + (size_t)blockIdx.x * TILE_FLOATS;
    float*       gdst = out + (size_t)blockIdx.x * TILE_FLOATS;

    // ---- Load phase: 256-bit coalesced streaming loads ----
    #pragma unroll
    for (int k = 0; k < V8_PER_THREAD; ++k) {
        int idx8 = k * TPB + threadIdx.x;          // 0..767 (x8 floats)
        float r[8];
        ldg256_cs(gsrc + idx8 * 8, r);
        float4* s4 = reinterpret_cast<float4*>(s) + idx8 * 2;
        s4[0] = make_float4(r[0], r[1], r[2], r[3]);
        s4[1] = make_float4(r[4], r[5], r[6], r[7]);
    }
    __syncthreads();

    // Broadcast constants; fold gamma into M, negate beta.
    float g0 = __ldg(&gamma[0]), g1 = __ldg(&gamma[1]), g2 = __ldg(&gamma[2]);
    float c00 = __ldg(&M[0]) * g0, c01 = __ldg(&M[1]) * g1, c02 = __ldg(&M[2]) * g2;
    float c10 = __ldg(&M[3]) * g0, c11 = __ldg(&M[4]) * g1, c12 = __ldg(&M[5]) * g2;
    float c20 = __ldg(&M[6]) * g0, c21 = __ldg(&M[7]) * g1, c22 = __ldg(&M[8]) * g2;
    float nb0 = -__ldg(&beta[0]), nb1 = -__ldg(&beta[1]), nb2 = -__ldg(&beta[2]);

    // ---- Compute phase: thread t handles pixel-groups t and t+256.
    // LDS.128 float-stride 12 across lanes -> banks (12t mod 32) distinct
    // within each 8-lane phase -> conflict-free.
    float4* s4 = reinterpret_cast<float4*>(s);
    #pragma unroll
    for (int pass = 0; pass < 2; ++pass) {
        int g = pass * TPB + threadIdx.x;          // 0..511
        float4 va = s4[3 * g + 0];
        float4 vb = s4[3 * g + 1];
        float4 vc = s4[3 * g + 2];

        float in[12] = { va.x, va.y, va.z, va.w,
                         vb.x, vb.y, vb.z, vb.w,
                         vc.x, vc.y, vc.z, vc.w };
        float ov[12];

        #pragma unroll
        for (int p = 0; p < 4; ++p) {
            float l0 = __logf(in[3 * p + 0] + 1e-6f);
            float l1 = __logf(in[3 * p + 1] + 1e-6f);
            float l2 = __logf(in[3 * p + 2] + 1e-6f);

            float u0 = fmaf(l0, c00, fmaf(l1, c10, fmaf(l2, c20, nb0)));
            float u1 = fmaf(l0, c01, fmaf(l1, c11, fmaf(l2, c21, nb1)));
            float u2 = fmaf(l0, c02, fmaf(l1, c12, fmaf(l2, c22, nb2)));

            ov[3 * p + 0] = __saturatef(__expf(u0));
            ov[3 * p + 1] = __saturatef(__expf(u1));
            ov[3 * p + 2] = __saturatef(__expf(u2));
        }

        s4[3 * g + 0] = make_float4(ov[0], ov[1], ov[2],  ov[3]);
        s4[3 * g + 1] = make_float4(ov[4], ov[5], ov[6],  ov[7]);
        s4[3 * g + 2] = make_float4(ov[8], ov[9], ov[10], ov[11]);
    }
    __syncthreads();

    // ---- Store phase: 256-bit coalesced streaming stores ----
    #pragma unroll
    for (int k = 0; k < V8_PER_THREAD; ++k) {
        int idx8 = k * TPB + threadIdx.x;
        float4 a = s4[idx8 * 2 + 0];
        float4 b = s4[idx8 * 2 + 1];
        float r[8] = { a.x, a.y, a.z, a.w, b.x, b.y, b.z, b.w };
        stg256_cs(gdst + idx8 * 8, r);
    }
}

// Scalar tail for leftover elements (none for the bench shape; kept for robustness).
__global__ void stain_norm_tail_kernel(const float* __restrict__ x,
                                       const float* __restrict__ M,
                                       const float* __restrict__ gamma,
                                       const float* __restrict__ beta,
                                       float* __restrict__ out,
                                       int start_elem, int n_elem)
{
    int e = start_elem + blockIdx.x * blockDim.x + threadIdx.x;
    if (e >= n_elem) return;
    int pix = e / 3;
    int d = e - pix * 3;
    float l0 = __logf(x[pix * 3 + 0] + 1e-6f);
    float l1 = __logf(x[pix * 3 + 1] + 1e-6f);
    float l2 = __logf(x[pix * 3 + 2] + 1e-6f);
    float gd = __ldg(&gamma[d]);
    float u = fmaf(l0, __ldg(&M[0 * 3 + d]) * gd,
             fmaf(l1, __ldg(&M[1 * 3 + d]) * gd,
             fmaf(l2, __ldg(&M[2 * 3 + d]) * gd, -__ldg(&beta[d]))));
    out[e] = __saturatef(__expf(u));
}

extern "C" void kernel_launch(void* const* d_in, const int* in_sizes, int n_in,
                              void* d_out, int out_size)
{
    const float* x     = (const float*)d_in[0];
    const float* M     = (const float*)d_in[1];
    const float* gamma = (const float*)d_in[2];
    const float* beta  = (const float*)d_in[3];
    float* out = (float*)d_out;

    int n_elem  = in_sizes[0];
    int n_tiles = n_elem / TILE_FLOATS;

    if (n_tiles > 0) {
        stain_norm_v8_kernel<<<n_tiles, TPB>>>(x, M, gamma, beta, out);
    }

    int done = n_tiles * TILE_FLOATS;   // multiple of 12 -> pixel-aligned
    int rem = n_elem - done;
    if (rem > 0) {
        int threads = 256;
        int blocks = (rem + threads - 1) / threads;
        stain_norm_tail_kernel<<<blocks, threads>>>(x, M, gamma, beta, out, done, n_elem);
    }
}

// round 8
// speedup vs baseline: 1.0548x; 1.0548x over previous
#include <cuda_runtime.h>

// Stain normalization: out = clip(exp(-((-log(x+1e-6)) @ M * gamma + beta)), 0, 1)
// Algebraically folded: out = sat(exp( log(x+1e-6) @ C - beta )), C[c][d] = M[c][d]*gamma[d]
//
// FINAL FORM (best measured: 63.49 us wall). This workload is at the sustained
// HBM mixed-read/write floor: 403 MB moved at ~6.34 TB/s effective. Five
// structural variants (direct strided, smem-staged, TMA load+store, TMA+stcs,
// 256-bit v8) all converge to the same wall time; compute pipes sit at ~25%.
//
// Structure: coalesced 128-bit streaming global loads -> smem; in-place compute
// with conflict-free stride-12 LDS.128 (banks 12t mod 32 distinct per 8-lane
// phase); coalesced 128-bit streaming stores. 24 KB tile, 256 threads, 8 CTAs/SM.

constexpr int TPB = 256;
constexpr int F4_PER_THREAD = 3;                  // 12 floats = 4 pixels per thread
constexpr int F4_PER_BLOCK = TPB * F4_PER_THREAD; // 768 float4 = 12 KB... per pass; see below

__global__ __launch_bounds__(TPB)
void stain_norm_smem_kernel(const float4* __restrict__ x4,
                            const float*  __restrict__ M,      // 3x3 row-major
                            const float*  __restrict__ gamma,  // 3
                            const float*  __restrict__ beta,   // 3
                            float4* __restrict__ out4,
                            int n_groups)                      // 4-pixel groups total
{
    __shared__ float4 s[F4_PER_BLOCK];

    const int group_base = blockIdx.x * TPB;          // first group of this block
    const int f4_base    = group_base * 3;            // first float4 of this block
    const int n_f4       = n_groups * 3;              // total float4 count

    // ---- Load phase: fully coalesced streaming loads ----
    #pragma unroll
    for (int k = 0; k < F4_PER_THREAD; ++k) {
        int idx = k * TPB + threadIdx.x;
        int g = f4_base + idx;
        if (g < n_f4) s[idx] = __ldcs(&x4[g]);
    }
    __syncthreads();

    // ---- Compute phase (in place; each thread's 12 floats are private) ----
    if (group_base + threadIdx.x < n_groups) {
        // Broadcast constants; fold gamma into M, negate beta.
        float g0 = __ldg(&gamma[0]), g1 = __ldg(&gamma[1]), g2 = __ldg(&gamma[2]);
        float c00 = __ldg(&M[0]) * g0, c01 = __ldg(&M[1]) * g1, c02 = __ldg(&M[2]) * g2;
        float c10 = __ldg(&M[3]) * g0, c11 = __ldg(&M[4]) * g1, c12 = __ldg(&M[5]) * g2;
        float c20 = __ldg(&M[6]) * g0, c21 = __ldg(&M[7]) * g1, c22 = __ldg(&M[8]) * g2;
        float nb0 = -__ldg(&beta[0]), nb1 = -__ldg(&beta[1]), nb2 = -__ldg(&beta[2]);

        float4 va = s[3 * threadIdx.x + 0];
        float4 vb = s[3 * threadIdx.x + 1];
        float4 vc = s[3 * threadIdx.x + 2];

        float in[12] = { va.x, va.y, va.z, va.w,
                         vb.x, vb.y, vb.z, vb.w,
                         vc.x, vc.y, vc.z, vc.w };
        float ov[12];

        #pragma unroll
        for (int p = 0; p < 4; ++p) {
            // l = log(x + 1e-6)   (negation folded into the exp sign)
            float l0 = __logf(in[3 * p + 0] + 1e-6f);
            float l1 = __logf(in[3 * p + 1] + 1e-6f);
            float l2 = __logf(in[3 * p + 2] + 1e-6f);

            // u_d = l0*C0d + l1*C1d + l2*C2d - beta_d ;  out = sat(exp(u_d))
            float u0 = fmaf(l0, c00, fmaf(l1, c10, fmaf(l2, c20, nb0)));
            float u1 = fmaf(l0, c01, fmaf(l1, c11, fmaf(l2, c21, nb1)));
            float u2 = fmaf(l0, c02, fmaf(l1, c12, fmaf(l2, c22, nb2)));

            ov[3 * p + 0] = __saturatef(__expf(u0));
            ov[3 * p + 1] = __saturatef(__expf(u1));
            ov[3 * p + 2] = __saturatef(__expf(u2));
        }

        s[3 * threadIdx.x + 0] = make_float4(ov[0], ov[1], ov[2],  ov[3]);
        s[3 * threadIdx.x + 1] = make_float4(ov[4], ov[5], ov[6],  ov[7]);
        s[3 * threadIdx.x + 2] = make_float4(ov[8], ov[9], ov[10], ov[11]);
    }
    __syncthreads();

    // ---- Store phase: fully coalesced, streaming (evict-first) ----
    #pragma unroll
    for (int k = 0; k < F4_PER_THREAD; ++k) {
        int idx = k * TPB + threadIdx.x;
        int g = f4_base + idx;
        if (g < n_f4) __stcs(&out4[g], s[idx]);
    }
}

// Scalar tail for leftover elements (n_elem not divisible by 12).
__global__ void stain_norm_tail_kernel(const float* __restrict__ x,
                                       const float* __restrict__ M,
                                       const float* __restrict__ gamma,
                                       const float* __restrict__ beta,
                                       float* __restrict__ out,
                                       int start_elem, int n_elem)
{
    int e = start_elem + blockIdx.x * blockDim.x + threadIdx.x;
    if (e >= n_elem) return;
    int pix = e / 3;
    int d = e - pix * 3;
    float l0 = __logf(x[pix * 3 + 0] + 1e-6f);
    float l1 = __logf(x[pix * 3 + 1] + 1e-6f);
    float l2 = __logf(x[pix * 3 + 2] + 1e-6f);
    float gd = __ldg(&gamma[d]);
    float u = fmaf(l0, __ldg(&M[0 * 3 + d]) * gd,
             fmaf(l1, __ldg(&M[1 * 3 + d]) * gd,
             fmaf(l2, __ldg(&M[2 * 3 + d]) * gd, -__ldg(&beta[d]))));
    out[e] = __saturatef(__expf(u));
}

extern "C" void kernel_launch(void* const* d_in, const int* in_sizes, int n_in,
                              void* d_out, int out_size)
{
    const float* x     = (const float*)d_in[0];
    const float* M     = (const float*)d_in[1];
    const float* gamma = (const float*)d_in[2];
    const float* beta  = (const float*)d_in[3];
    float* out = (float*)d_out;

    int n_elem = in_sizes[0];            // total floats (B*H*W*3)
    int n_groups = n_elem / 12;          // 4-pixel (12-float) groups

    if (n_groups > 0) {
        int blocks = (n_groups + TPB - 1) / TPB;
        stain_norm_smem_kernel<<<blocks, TPB>>>(
            (const float4*)x, M, gamma, beta, (float4*)out, n_groups);
    }

    int done = n_groups * 12;
    int rem = n_elem - done;
    if (rem > 0) {
        int threads = 256;
        int blocks = (rem + threads - 1) / threads;
        stain_norm_tail_kernel<<<blocks, threads>>>(x, M, gamma, beta, out, done, n_elem);
    }
}